// round 4
// baseline (speedup 1.0000x reference)
#include <cuda_runtime.h>
#include <cuda_bf16.h>

// DTW 2048x2048 anti-diagonal wavefront, 2-CTA cluster (2 SMs).
// CTA c owns rows [1024c, 1024c+1024): 8 warps x 32 lanes x 4 rows/thread.
// Intra-CTA: R2's warp-skew pipeline (smem ring + cta-scope acquire/release
// progress counters, one check per 16-diagonal batch). Cross-CTA (one
// boundary): CTA0 warp7 stores per-diagonal boundary values into CTA1's
// ring[0] via weak st.shared::cluster, then one st.release.cluster counter
// per batch; CTA1 warp0 spins on the LOCAL counter with ld.relaxed.cluster
// and upgrades with a single fence.acq_rel.cluster on success. Backpressure
// mirrored upstream the same way. Cluster-scope traffic: ~2 ops/batch on 2
// of 16 warps only (R3's mistake was cluster-scope acquires everywhere).
//
// Recurrence per diagonal d, thread rows r=0..3:
//   n[r] = (x[r]-y[d-i0-r])^2 + min(up, left, diag)   (all register-resident
// except each warp's top row: shfl_up + ring). Out-of-range cells stay +inf
// (left) or finite garbage that only flows rightward (right) -- never into
// valid cells. y staged zero-padded in smem; 4-deep time-indexed register
// queue => 1 LDS of y per thread per step.

#define NLEN  2048
#define NC    2
#define NW    8
#define RPT   4
#define KB    16
#define NB    255           // full batches (255*16 = 4080)
#define TAIL  15            // 4080 + 15 = 4095 diagonals
#define SRING 64
#define FINF  __int_as_float(0x7f800000)

__device__ __forceinline__ unsigned smem_u32(const void* p) {
    return (unsigned)__cvta_generic_to_shared(p);
}
__device__ __forceinline__ unsigned mapa_u32(unsigned addr, unsigned rank) {
    unsigned r;
    asm("mapa.shared::cluster.u32 %0, %1, %2;" : "=r"(r) : "r"(addr), "r"(rank));
    return r;
}
__device__ __forceinline__ int ld_acq_cta(const int* p) {
    int v; unsigned a = smem_u32(p);
    asm volatile("ld.acquire.cta.shared::cta.b32 %0, [%1];" : "=r"(v) : "r"(a) : "memory");
    return v;
}
__device__ __forceinline__ int ld_rlx_cluster(const int* p) {
    int v; unsigned a = smem_u32(p);
    asm volatile("ld.relaxed.cluster.shared::cta.b32 %0, [%1];" : "=r"(v) : "r"(a) : "memory");
    return v;
}
__device__ __forceinline__ void fence_acq_cluster() {
    asm volatile("fence.acq_rel.cluster;" ::: "memory");
}
__device__ __forceinline__ void st_rel_cta(int* p, int v) {
    unsigned a = smem_u32(p);
    asm volatile("st.release.cta.shared::cta.b32 [%0], %1;" :: "r"(a), "r"(v) : "memory");
}
__device__ __forceinline__ void st_rel_cluster_rem(unsigned a, int v) {
    asm volatile("st.release.cluster.shared::cluster.b32 [%0], %1;" :: "r"(a), "r"(v) : "memory");
}
__device__ __forceinline__ void st_f32_rem(unsigned a, float v) {
    asm volatile("st.shared::cluster.f32 [%0], %1;" :: "r"(a), "f"(v) : "memory");
}
__device__ __forceinline__ void cluster_sync_() {
    asm volatile("barrier.cluster.arrive.aligned;" ::: "memory");
    asm volatile("barrier.cluster.wait.aligned;" ::: "memory");
}
__device__ __forceinline__ unsigned ctarank_() {
    unsigned r; asm("mov.u32 %0, %%cluster_ctarank;" : "=r"(r)); return r;
}

__global__ __launch_bounds__(NW * 32, 1) __cluster_dims__(NC, 1, 1)
void dtw_cluster2_kernel(const float* __restrict__ x,
                         const float* __restrict__ y,
                         float* __restrict__ out)
{
    __shared__ float ysp[3 * NLEN];         // ysp[NLEN + j] = y[j], pads = 0
    __shared__ float ring[NW + 1][SRING];   // ring[0]: from upstream CTA (or +inf)
    __shared__ int   prog[NW + 2];          // [0]=upstream, [1..NW]=local, [NW+1]=downstream

    const int t    = threadIdx.x;
    const int lane = t & 31;
    const int w    = t >> 5;
    const unsigned rank = ctarank_();
    const bool has_prev = (rank != 0);
    const bool has_next = (rank != NC - 1);

    for (int k = t; k < 3 * NLEN; k += NW * 32) {
        int j = k - NLEN;
        ysp[k] = ((unsigned)j < (unsigned)NLEN) ? y[j] : 0.0f;
    }
    for (int k = t; k < (NW + 1) * SRING; k += NW * 32)
        (&ring[0][0])[k] = FINF;
    if (t < NW + 2) {
        int v = -1;
        if (t == 0      && !has_prev) v = 0x7fffffff;
        if (t == NW + 1 && !has_next) v = 0x7fffffff;
        prog[t] = v;
    }

    const int i0 = (int)rank * 1024 + w * 128 + lane * RPT;

    float xv[RPT];
    {
        float4 a = reinterpret_cast<const float4*>(x + i0)[0];
        xv[0] = a.x; xv[1] = a.y; xv[2] = a.z; xv[3] = a.w;
    }

    float p[RPT], pp[RPT], yq[RPT];
    #pragma unroll
    for (int r = 0; r < RPT; ++r) { p[r] = FINF; pp[r] = FINF; }
    float dTop = (rank == 0 && t == 0) ? 0.0f : FINF;

    unsigned rem_ring0 = 0, rem_prog0 = 0, rem_progN1 = 0;
    if (w == NW - 1 && has_next) {
        rem_ring0 = mapa_u32(smem_u32(&ring[0][0]), rank + 1);
        rem_prog0 = mapa_u32(smem_u32(&prog[0]),    rank + 1);
    }
    if (w == 0 && has_prev) {
        rem_progN1 = mapa_u32(smem_u32(&prog[NW + 1]), rank - 1);
    }

    cluster_sync_();

    const float* yb = ysp + NLEN - i0;
    yq[3] = yb[-1]; yq[2] = yb[-2]; yq[1] = yb[-3]; yq[0] = 0.0f;

    const float* ringprev = ring[w];
    float*       ringself = ring[w + 1];
    const bool   last_warp = (w == NW - 1);
    const bool   v1_remote = has_prev && (w == 0);        // prog[w] written by remote CTA
    const bool   v2_remote = has_next && (w == NW - 1);   // prog[w+2] written by remote CTA

    #define STEP_BODY(u)                                                        \
        {                                                                       \
            const float yn = ybb[(u)];                                          \
            yq[(u) & 3] = yn;                                                   \
            float up = __shfl_up_sync(0xffffffffu, p[RPT - 1], 1);              \
            if (lane == 0) up = ((u) == 0) ? up_first : rpb[(u) - 1];           \
            float nv[RPT];                                                      \
            {                                                                   \
                const float dy = xv[0] - yn;                                    \
                nv[0] = fmaf(dy, dy, fminf(fminf(up, dTop), p[0]));             \
            }                                                                   \
            _Pragma("unroll")                                                   \
            for (int r = 1; r < RPT; ++r) {                                     \
                const float dy = xv[r] - yq[((u) - r) & 3];                     \
                nv[r] = fmaf(dy, dy, fminf(fminf(p[r - 1], pp[r - 1]), p[r]));  \
            }                                                                   \
            if (lane == 31) {                                                   \
                if (!last_warp)    rs[(u)] = nv[RPT - 1];                       \
                else if (has_next) st_f32_rem(rrs + (unsigned)((u) << 2), nv[RPT - 1]); \
            }                                                                   \
            dTop = up;                                                          \
            _Pragma("unroll")                                                   \
            for (int r = 0; r < RPT; ++r) { pp[r] = p[r]; p[r] = nv[r]; }       \
        }

    for (int m = 0; m <= NB; ++m) {
        const int d0    = m * KB;
        const int steps = (m == NB) ? TAIL : KB;
        const int need1 = d0 + steps - 2;
        const int need2 = d0 + steps - 1 - (SRING - 1);

        int v1, v2;
        do {
            v1 = v1_remote ? ld_rlx_cluster(prog + w)     : ld_acq_cta(prog + w);
            v2 = v2_remote ? ld_rlx_cluster(prog + w + 2) : ld_acq_cta(prog + w + 2);
        } while (v1 < need1 || v2 < need2);
        if (v1_remote | v2_remote) fence_acq_cluster();

        const float* ybb = yb + d0;
        float*       rs  = ringself + (d0 & (SRING - 1));
        const float* rpb = ringprev + (d0 & (SRING - 1));
        const unsigned rrs = rem_ring0 + (unsigned)((d0 & (SRING - 1)) << 2);
        const float  up_first = ringprev[(d0 - 1) & (SRING - 1)];

        if (m < NB) {
            #pragma unroll
            for (int u = 0; u < KB; ++u) STEP_BODY(u)
        } else {
            #pragma unroll
            for (int u = 0; u < TAIL; ++u) STEP_BODY(u)
        }

        const int done = d0 + steps - 1;
        if (lane == 31) {
            st_rel_cta(prog + w + 1, done);
            if (last_warp && has_next) st_rel_cluster_rem(rem_prog0, done);
            if (w == 0 && has_prev)    st_rel_cluster_rem(rem_progN1, done);
        }
    }
    #undef STEP_BODY

    // Global last row 2047: CTA rank 1, warp 7, lane 31, r = 3.
    if (!has_next && t == NW * 32 - 1) out[0] = sqrtf(p[RPT - 1]);

    cluster_sync_();   // no CTA exits while a peer may still write its smem
}

extern "C" void kernel_launch(void* const* d_in, const int* in_sizes, int n_in,
                              void* d_out, int out_size)
{
    const float* x = (const float*)d_in[0];
    const float* y = (const float*)d_in[1];
    float* out = (float*)d_out;
    dtw_cluster2_kernel<<<NC, NW * 32>>>(x, y, out);
}

// round 6
// speedup vs baseline: 1.8364x; 1.8364x over previous
#include <cuda_runtime.h>
#include <cuda_bf16.h>

// DTW 2048x2048 anti-diagonal wavefront, single CTA, 8 warps, 8 rows/thread.
// R2 engine (warp-skew pipeline, smem ring + cta-scope acquire/release
// counters, 16-diagonal batches) with three upgrades:
//  1. y values batch-prefetched: 24 floats per batch via 6 aligned LDS.128
//     (kills the 8-way-conflicted, chain-exposed per-step scalar LDS).
//  2. ring values batch-prefetched: 20 floats via 5 broadcast LDS.128
//     (kills lane0's per-step LDS that gated the warp). Producer gate is
//     tightened by one batch (need2 += KB) so the prefetch can never race
//     a ring overwrite.
//  3. cost math packed as f32x2: add.rn.f32x2 / fma.rn.f32x2 over row pairs.
//     smem holds NEGATED y (dy = x + (-y)) in two copies, the second shifted
//     by one element, so both pair parities are 16B-aligned -> packs are
//     register-pair aliases, no MOVs.
// Out-of-range cells stay +inf (left edge) or finite garbage that only flows
// rightward (right edge) -- never into valid cells; no predicates needed.

#define NLEN  2048
#define NW    8
#define RPT   8
#define KB    16
#define NB    255           // full batches (255*16 = 4080)
#define TAIL  15            // 4080 + 15 = 4095 diagonals
#define SRING 64
#define FINF  __int_as_float(0x7f800000)

typedef unsigned long long u64t;

__device__ __forceinline__ unsigned smem_u32(const void* p) {
    return (unsigned)__cvta_generic_to_shared(p);
}
__device__ __forceinline__ int ld_acq(const int* p) {
    int v; unsigned a = smem_u32(p);
    asm volatile("ld.acquire.cta.shared::cta.b32 %0, [%1];" : "=r"(v) : "r"(a) : "memory");
    return v;
}
__device__ __forceinline__ void st_rel(int* p, int v) {
    unsigned a = smem_u32(p);
    asm volatile("st.release.cta.shared::cta.b32 [%0], %1;" :: "r"(a), "r"(v) : "memory");
}
__device__ __forceinline__ void lds128(float& a, float& b, float& c, float& d, unsigned addr) {
    asm volatile("ld.shared.v4.f32 {%0,%1,%2,%3}, [%4];"
                 : "=f"(a), "=f"(b), "=f"(c), "=f"(d) : "r"(addr));
}
__device__ __forceinline__ u64t pack2(float lo, float hi) {
    u64t r; asm("mov.b64 %0, {%1,%2};" : "=l"(r) : "f"(lo), "f"(hi)); return r;
}
__device__ __forceinline__ void unpack2(float& lo, float& hi, u64t v) {
    asm("mov.b64 {%0,%1}, %2;" : "=f"(lo), "=f"(hi) : "l"(v));
}
__device__ __forceinline__ u64t add2(u64t a, u64t b) {
    u64t r; asm("add.rn.f32x2 %0, %1, %2;" : "=l"(r) : "l"(a), "l"(b)); return r;
}
__device__ __forceinline__ u64t fma2(u64t a, u64t b, u64t c) {
    u64t r; asm("fma.rn.f32x2 %0, %1, %2, %3;" : "=l"(r) : "l"(a), "l"(b), "l"(c)); return r;
}

__global__ __launch_bounds__(NW * 32, 1)
void dtw_pf_kernel(const float* __restrict__ x,
                   const float* __restrict__ y,
                   float* __restrict__ out)
{
    // dynamic smem: [0, 3N) = yspA (negated y, padded), [3N, 6N) = yspB (shifted by 1)
    extern __shared__ float dyn[];
    float* yspA = dyn;
    float* yspB = dyn + 3 * NLEN;

    __shared__ __align__(16) float ring[NW + 1][SRING];
    __shared__ int prog[NW + 2];

    const int t    = threadIdx.x;
    const int lane = t & 31;
    const int w    = t >> 5;

    // yspA[k] = -y[k - NLEN] (0 outside), yspB[k] = yspA value at k+1
    for (int k = t; k < 3 * NLEN; k += NW * 32) {
        int j = k - NLEN;
        yspA[k] = ((unsigned)j < (unsigned)NLEN) ? -y[j] : 0.0f;
        int j2 = k + 1 - NLEN;
        yspB[k] = ((unsigned)j2 < (unsigned)NLEN) ? -y[j2] : 0.0f;
    }
    for (int k = t; k < (NW + 1) * SRING; k += NW * 32)
        (&ring[0][0])[k] = FINF;           // ring[0] = phantom producer (+inf)
    if (t < NW + 2)
        prog[t] = (t == 0 || t == NW + 1) ? 0x7fffffff : -1;

    const int i0 = w * 256 + lane * RPT;   // this thread's top row

    u64t x2[4];
    {
        float4 a = reinterpret_cast<const float4*>(x + i0)[0];
        float4 b = reinterpret_cast<const float4*>(x + i0)[1];
        x2[0] = pack2(a.y, a.x);   // lo = row 2pr+1, hi = row 2pr
        x2[1] = pack2(a.w, a.z);
        x2[2] = pack2(b.y, b.x);
        x2[3] = pack2(b.w, b.z);
    }

    float p[RPT], pp[RPT];
    #pragma unroll
    for (int r = 0; r < RPT; ++r) { p[r] = FINF; pp[r] = FINF; }
    float dTop = (t == 0) ? 0.0f : FINF;   // virtual DTW[-1][-1]=0 seeds (0,0)

    __syncthreads();

    const unsigned yAaddr = smem_u32(yspA) + (unsigned)((NLEN - i0 - 8) << 2);
    const unsigned yBaddr = smem_u32(yspB) + (unsigned)((NLEN - i0 - 8) << 2);
    const unsigned rpaddr = smem_u32(&ring[w][0]);
    float* ringself = ring[w + 1];

    #define STEP_BODY(u)                                                          \
        {                                                                         \
            float up_sh = __shfl_up_sync(0xffffffffu, p[RPT - 1], 1);             \
            float up = (lane == 0) ? bu[(u) + 3] : up_sh;                         \
            float nv[RPT];                                                        \
            _Pragma("unroll")                                                     \
            for (int pr = 0; pr < 4; ++pr) {                                      \
                const int a = 2 * pr, b = 2 * pr + 1;                             \
                const int klo = 7 + (u) - 2 * pr;                                 \
                u64t y2 = (klo & 1) ? pack2(yO[klo - 1], yO[klo])                 \
                                    : pack2(yE[klo], yE[klo + 1]);                \
                u64t dy2 = add2(x2[pr], y2);                                      \
                float mhi = (a == 0) ? fminf(fminf(up, dTop), p[0])               \
                                     : fminf(fminf(p[a - 1], pp[a - 1]), p[a]);   \
                float mlo = fminf(fminf(p[b - 1], pp[b - 1]), p[b]);              \
                u64t nv2 = fma2(dy2, dy2, pack2(mlo, mhi));                       \
                unpack2(nv[b], nv[a], nv2);                                       \
            }                                                                     \
            if (lane == 31) rs[(u)] = nv[RPT - 1];                                \
            dTop = up;                                                            \
            _Pragma("unroll")                                                     \
            for (int r = 0; r < RPT; ++r) { pp[r] = p[r]; p[r] = nv[r]; }         \
        }

    for (int m = 0; m <= NB; ++m) {
        const int d0    = m * KB;
        const int steps = (m == NB) ? TAIL : KB;
        const int need1 = d0 + steps - 2;                      // upstream wrote this far
        const int need2 = d0 + steps - 1 - (SRING - 1) + KB;   // +KB: prefetch race guard
        int v1, v2;
        do { v1 = ld_acq(prog + w); v2 = ld_acq(prog + w + 2); }
        while (v1 < need1 || v2 < need2);

        // Ring prefetch: bu[k] = ringprev value at diagonal d0-4+k (broadcast LDS).
        float bu[20];
        #pragma unroll
        for (int v = 0; v < 5; ++v) {
            unsigned s = (unsigned)((d0 - 4 + 4 * v) & (SRING - 1));
            lds128(bu[4*v], bu[4*v+1], bu[4*v+2], bu[4*v+3], rpaddr + (s << 2));
        }
        // y prefetch: window d0-8 .. d0+15 (negated y), both pair alignments.
        float yE[24], yO[24];
        {
            unsigned ba = yAaddr + (unsigned)(d0 << 2);
            unsigned bb = yBaddr + (unsigned)(d0 << 2);
            #pragma unroll
            for (int v = 0; v < 6; ++v) {
                lds128(yE[4*v], yE[4*v+1], yE[4*v+2], yE[4*v+3], ba + 16u * v);
                lds128(yO[4*v], yO[4*v+1], yO[4*v+2], yO[4*v+3], bb + 16u * v);
            }
        }

        float* rs = ringself + (d0 & (SRING - 1));   // no wrap within a batch

        if (m < NB) {
            #pragma unroll
            for (int u = 0; u < KB; ++u) STEP_BODY(u)
        } else {
            #pragma unroll
            for (int u = 0; u < TAIL; ++u) STEP_BODY(u)
        }

        if (lane == 31) st_rel(prog + w + 1, d0 + steps - 1);
    }
    #undef STEP_BODY

    // Warp 7, lane 31, bottom row 2047: value at d = 4094 is p[7] after rotation.
    if (t == NW * 32 - 1) out[0] = sqrtf(p[RPT - 1]);
}

extern "C" void kernel_launch(void* const* d_in, const int* in_sizes, int n_in,
                              void* d_out, int out_size)
{
    const float* x = (const float*)d_in[0];
    const float* y = (const float*)d_in[1];
    float* out = (float*)d_out;
    const int dynbytes = 2 * 3 * NLEN * sizeof(float);   // 48 KB
    cudaFuncSetAttribute(dtw_pf_kernel, cudaFuncAttributeMaxDynamicSharedMemorySize, dynbytes);
    dtw_pf_kernel<<<1, NW * 32, dynbytes>>>(x, y, out);
}